// round 1
// baseline (speedup 1.0000x reference)
#include <cuda_runtime.h>
#include <math_constants.h>

#define NF 8
#define NQ 300
#define HH 96
#define WW 96
#define HW (HH*WW)        // 9216
#define FHW (NF*HW)       // 73728
#define ALPHA_C 0.25f
#define EPSV 1e-8f
#define PITCH 97

// Per-batch target precomputations (no allocation allowed -> device globals)
__device__ float g_tgtx[2][NF*HH];     // max over w per (f,h)
__device__ float g_tgty[2][NF*WW];     // max over h per (f,w)
__device__ float g_tsum[2];            // sum of tmask
__device__ float g_tgtx_sum[2];
__device__ float g_tgty_sum[2];

__device__ __forceinline__ float sigmoid_fast(float x) {
    float a = fabsf(x);
    float u = __expf(-a);
    float r = __fdividef(1.0f, 1.0f + u);
    return (x >= 0.0f) ? r : u * r;
}

__device__ __forceinline__ float warp_sum(float v) {
    #pragma unroll
    for (int o = 16; o; o >>= 1) v += __shfl_xor_sync(0xffffffff, v, o);
    return v;
}

// ---------------------------------------------------------------------------
// Prep: per-batch target maxes and sums. grid=2 (one per b), block=768
// ---------------------------------------------------------------------------
__global__ void prep_kernel(const float* __restrict__ tmask) {
    int b = blockIdx.x;
    int tid = threadIdx.x;              // 0..767 -> (f, h) and (f, w)
    const float* base = tmask + (size_t)b * FHW;

    int f = tid / HH;
    int h = tid % HH;
    const float* row = base + (size_t)(f * HH + h) * WW;
    float rmax = -CUDART_INF_F, rsum = 0.0f;
    #pragma unroll 4
    for (int w = 0; w < WW; ++w) { float v = row[w]; rmax = fmaxf(rmax, v); rsum += v; }
    g_tgtx[b][tid] = rmax;

    int w = tid % WW;
    const float* colb = base + (size_t)f * HW + w;
    float cmax = -CUDART_INF_F;
    #pragma unroll 4
    for (int h2 = 0; h2 < HH; ++h2) cmax = fmaxf(cmax, colb[h2 * WW]);
    g_tgty[b][tid] = cmax;

    // reduce rsum (total mask sum), rmax (sum of tgtx), cmax (sum of tgty)
    __shared__ float red[24][3];
    float s0 = warp_sum(rsum);
    float s1 = warp_sum(rmax);
    float s2 = warp_sum(cmax);
    int wid = tid >> 5, lane = tid & 31;
    if (lane == 0) { red[wid][0] = s0; red[wid][1] = s1; red[wid][2] = s2; }
    __syncthreads();
    if (tid == 0) {
        float t0 = 0, t1 = 0, t2 = 0;
        for (int i = 0; i < 24; ++i) { t0 += red[i][0]; t1 += red[i][1]; t2 += red[i][2]; }
        g_tsum[b] = t0; g_tgtx_sum[b] = t1; g_tgty_sum[b] = t2;
    }
}

// ---------------------------------------------------------------------------
// Main cost kernel: one block per (b, q). block = 384 = 4 x 96
// ---------------------------------------------------------------------------
__global__ __launch_bounds__(384) void cost_kernel(
    const float* __restrict__ logits,   // (2,8,300,1)
    const float* __restrict__ boxes,    // (2,8,300,4)
    const float* __restrict__ masks,    // (2,8,300,96,96)
    const float* __restrict__ tmask,    // (2,8,96,96)
    const float* __restrict__ tbox,     // (2,8,4)
    const int*   __restrict__ tvalid,   // (2,8)
    const unsigned char* __restrict__ vpad, // (2,96,96) bool
    float* __restrict__ C)              // (2,300)
{
    int blk = blockIdx.x;
    int b = blk / NQ, q = blk % NQ;
    int tid = threadIdx.x;

    __shared__ float tile[HH * PITCH];
    __shared__ float rowmax[NF * HH];   // src_x flat (f,h)
    __shared__ float colmax[NF * WW];   // src_y flat (f,w)
    __shared__ float red[12][7];

    int w0 = tid % WW;                  // fixed column per thread
    int h0 = tid / WW;                  // 0..3, rows h0+4k

    float facc = 0.0f, nacc = 0.0f, sacc = 0.0f;

    for (int f = 0; f < NF; ++f) {
        const float* mb = masks + (size_t)((b * NF + f) * NQ + q) * HW;
        const float* tb = tmask + (size_t)(b * NF + f) * HW;
        const unsigned char* vb = vpad + (size_t)b * HW;
        #pragma unroll
        for (int k = 0; k < 24; ++k) {
            int h = h0 + 4 * k;
            int idx = h * WW + w0;
            float x = mb[idx];
            if (vb[idx]) x = 0.0f;
            float t = tb[idx];

            float a = fabsf(x);
            float u = __expf(-a);
            float r = __fdividef(1.0f, 1.0f + u);
            float p = (x >= 0.0f) ? r : u * r;        // sigmoid(x)
            float sp = __logf(1.0f + u);              // log1p(exp(-|x|))
            float ce = fmaxf(x, 0.0f) - x * t + sp;
            float omp = t + p - 2.0f * p * t;         // 1 - p_t
            float at = 0.75f - 0.5f * t;              // alpha_t
            facc += at * ce * omp * omp;
            nacc += p * t;
            sacc += p;
            tile[h * PITCH + w0] = x;
        }
        __syncthreads();
        // row / col maxes of this frame
        if (tid < 192) {
            int r_ = tid >> 1, half = tid & 1;
            float m = -CUDART_INF_F;
            const float* rp = tile + r_ * PITCH + half * 48;
            #pragma unroll
            for (int w = 0; w < 48; ++w) m = fmaxf(m, rp[w]);
            m = fmaxf(m, __shfl_xor_sync(0xffffffff, m, 1));
            if (!half) rowmax[f * HH + r_] = m;
        } else {
            int t2 = tid - 192;
            int c_ = t2 >> 1, half = t2 & 1;
            float m = -CUDART_INF_F;
            const float* cp = tile + (half * 48) * PITCH + c_;
            #pragma unroll
            for (int h = 0; h < 48; ++h) m = fmaxf(m, cp[h * PITCH]);
            m = fmaxf(m, __shfl_xor_sync(0xffffffff, m, 1));
            if (!half) colmax[f * WW + c_] = m;
        }
        __syncthreads();
    }

    // projection dice partial sums over 768 elements each
    float sx = 0, nx = 0, sy = 0, ny = 0;
    #pragma unroll
    for (int j = tid; j < NF * HH; j += 384) {
        float px = sigmoid_fast(rowmax[j]);
        sx += px; nx += px * g_tgtx[b][j];
        float py = sigmoid_fast(colmax[j]);
        sy += py; ny += py * g_tgty[b][j];
    }

    // block reduce 7 accumulators
    float v0 = warp_sum(facc), v1 = warp_sum(nacc), v2 = warp_sum(sacc);
    float v3 = warp_sum(sx),   v4 = warp_sum(nx);
    float v5 = warp_sum(sy),   v6 = warp_sum(ny);
    int wid = tid >> 5, lane = tid & 31;
    if (lane == 0) {
        red[wid][0] = v0; red[wid][1] = v1; red[wid][2] = v2;
        red[wid][3] = v3; red[wid][4] = v4; red[wid][5] = v5; red[wid][6] = v6;
    }
    __syncthreads();

    if (tid == 0) {
        float t0=0,t1=0,t2=0,t3=0,t4=0,t5=0,t6=0;
        for (int i = 0; i < 12; ++i) {
            t0 += red[i][0]; t1 += red[i][1]; t2 += red[i][2];
            t3 += red[i][3]; t4 += red[i][4]; t5 += red[i][5]; t6 += red[i][6];
        }
        float cost_mask = t0 / (float)FHW;
        float cost_dice = -((2.0f * t1 + 1.0f) / (t2 + g_tsum[b] + 1.0f));
        float dx = (2.0f * t4 + 1.0f) / (t3 + g_tgtx_sum[b] + 1.0f);
        float dy = (2.0f * t6 + 1.0f) / (t5 + g_tgty_sum[b] + 1.0f);
        float cost_proj = -0.5f * (dy + dx);

        float cls = 0, wsum = 0, bbox = 0, giou = 0;
        for (int f = 0; f < NF; ++f) {
            float lg = logits[(b * NF + f) * NQ + q];
            float p = sigmoid_fast(lg);
            float neg = (1.0f - ALPHA_C) * p * p * (-__logf(1.0f - p + EPSV));
            float pos = ALPHA_C * (1.0f - p) * (1.0f - p) * (-__logf(p + EPSV));
            float wv = (tvalid[b * NF + f] != 0) ? 1.0f : 0.0f;
            cls += (pos - neg) * wv; wsum += wv;

            const float* bx = boxes + (size_t)((b * NF + f) * NQ + q) * 4;
            const float* tx = tbox + (size_t)(b * NF + f) * 4;
            bbox += fabsf(bx[0]-tx[0]) + fabsf(bx[1]-tx[1]) + fabsf(bx[2]-tx[2]) + fabsf(bx[3]-tx[3]);

            float sx0 = bx[0]-0.5f*bx[2], sy0 = bx[1]-0.5f*bx[3];
            float sx1 = bx[0]+0.5f*bx[2], sy1 = bx[1]+0.5f*bx[3];
            float tx0 = tx[0]-0.5f*tx[2], ty0 = tx[1]-0.5f*tx[3];
            float tx1 = tx[0]+0.5f*tx[2], ty1 = tx[1]+0.5f*tx[3];
            float a1 = (sx1-sx0)*(sy1-sy0);
            float a2 = (tx1-tx0)*(ty1-ty0);
            float iw = fmaxf(fminf(sx1,tx1) - fmaxf(sx0,tx0), 0.0f);
            float ih = fmaxf(fminf(sy1,ty1) - fmaxf(sy0,ty0), 0.0f);
            float inter = iw * ih;
            float uni = a1 + a2 - inter;
            float iou = inter / uni;
            float cw = fmaxf(fmaxf(sx1,tx1) - fminf(sx0,tx0), 0.0f);
            float ch = fmaxf(fmaxf(sy1,ty1) - fminf(sy0,ty0), 0.0f);
            float ac = cw * ch;
            giou += -(iou - (ac - uni) / ac);
        }
        float cost_class = cls / wsum;
        float cost_bbox  = bbox * (1.0f / NF);
        float cost_giou  = giou * (1.0f / NF);

        C[b * NQ + q] = cost_class + cost_bbox + cost_giou + cost_mask + cost_dice + cost_proj;
    }
}

// ---------------------------------------------------------------------------
// Argmin over queries per batch + tail writes. grid=2, block=256
// ---------------------------------------------------------------------------
__global__ void argmin_kernel(const float* __restrict__ C, float* __restrict__ out, int out_size) {
    int b = blockIdx.x;
    int tid = threadIdx.x;
    float best = CUDART_INF_F; int bi = NQ;
    for (int q = tid; q < NQ; q += blockDim.x) {
        float v = C[b * NQ + q];
        if (v < best || (v == best && q < bi)) { best = v; bi = q; }
    }
    #pragma unroll
    for (int o = 16; o; o >>= 1) {
        float ov = __shfl_down_sync(0xffffffff, best, o);
        int   oi = __shfl_down_sync(0xffffffff, bi,   o);
        if (ov < best || (ov == best && oi < bi)) { best = ov; bi = oi; }
    }
    __shared__ float sv[8]; __shared__ int si[8];
    int wid = tid >> 5, lane = tid & 31;
    if (lane == 0) { sv[wid] = best; si[wid] = bi; }
    __syncthreads();
    if (tid == 0) {
        int nw = blockDim.x >> 5;
        for (int i = 1; i < nw; ++i) {
            if (sv[i] < best || (sv[i] == best && si[i] < bi)) { best = sv[i]; bi = si[i]; }
        }
        // tail: src_ind (int64 in reference) then tgt_ind zeros
        if (out_size >= 608) {
            long long* op = (long long*)(out + 600);
            op[b] = (long long)bi;
            op[2 + b] = 0ll;
            if (b == 0) for (int i = 608; i < out_size; ++i) out[i] = 0.0f;
        } else if (out_size >= 604) {
            out[600 + b] = (float)bi;
            out[602 + b] = 0.0f;
            if (b == 0) for (int i = 604; i < out_size; ++i) out[i] = 0.0f;
        } else {
            if (b == 0) for (int i = 600; i < out_size; ++i) out[i] = 0.0f;
        }
    }
}

extern "C" void kernel_launch(void* const* d_in, const int* in_sizes, int n_in,
                              void* d_out, int out_size) {
    const float* logits = (const float*)d_in[0];
    const float* boxes  = (const float*)d_in[1];
    const float* masks  = (const float*)d_in[2];
    const float* tmask  = (const float*)d_in[3];
    const float* tbox   = (const float*)d_in[4];
    const int*   tvalid = (const int*)d_in[5];
    const unsigned char* vpad = (const unsigned char*)d_in[6];
    float* out = (float*)d_out;

    prep_kernel<<<2, 768>>>(tmask);
    cost_kernel<<<2 * NQ, 384>>>(logits, boxes, masks, tmask, tbox, tvalid, vpad, out);
    argmin_kernel<<<2, 256>>>(out, out, out_size);
}